// round 17
// baseline (speedup 1.0000x reference)
#include <cuda_runtime.h>
#include <cuda_fp16.h>
#include <cstdint>
#include <math_constants.h>

// VQ nearest-codebook via fused coarse+rescue argmin:
//  Pass 1: fp16 hh-only mma coarse scores (kept in registers); per-tile
//          band candidates (BAND=1.0 >= 2*coarse_err) rescored exactly in
//          fp32 inside the same kernel; per-segment winner -> packed key.
//  Pass 2: tiny merge over 4 segments + gather.
//   z_e_x: [16,2048,256] f32, embedding: [1024,256] f32
// d_out (f32): z_q_x [N*D] @0, z_q_x_bar @8388608, indices @16777216

#define NTOK   32768
#define DDIM   256
#define KCODE  1024
#define BM     128
#define BN     128
#define NSEG   4
#define SEGK   256
#define KS     32
#define NG     16              // 2 tiles * 8 stages
#define PITCHH 40
#define CAP    4096            // candidate list capacity per CTA

#define OUT_BAR   8388608
#define OUT_IDX  16777216
#define BAND   1.0f

#define MAT_H   (BM * PITCHH)            // 5120 halves per matrix-stage
#define DYN_SMEM (4 * MAT_H * 2)         // 40960 B (Ah x2, Bh x2)

typedef unsigned long long ull;

__device__ float g_cnorm[KCODE];
__device__ ull   g_candKey[NSEG * NTOK];

// ---------------------------------------------------------------------------
__device__ __forceinline__ uint32_t smem_u32(const void* p) {
    uint32_t a;
    asm("{ .reg .u64 t; cvta.to.shared.u64 t, %1; cvt.u32.u64 %0, t; }"
        : "=r"(a) : "l"(p));
    return a;
}
#define LDSM4(r, addr) \
    asm volatile("ldmatrix.sync.aligned.m8n8.x4.shared.b16 {%0,%1,%2,%3}, [%4];" \
        : "=r"((r)[0]), "=r"((r)[1]), "=r"((r)[2]), "=r"((r)[3]) : "r"(addr))

__device__ __forceinline__ void mma_f16(float* c, const uint32_t* a,
                                        uint32_t b0, uint32_t b1) {
    asm volatile(
        "mma.sync.aligned.m16n8k16.row.col.f32.f16.f16.f32 "
        "{%0,%1,%2,%3}, {%4,%5,%6,%7}, {%8,%9}, {%0,%1,%2,%3};"
        : "+f"(c[0]), "+f"(c[1]), "+f"(c[2]), "+f"(c[3])
        : "r"(a[0]), "r"(a[1]), "r"(a[2]), "r"(a[3]), "r"(b0), "r"(b1));
}

__device__ __forceinline__ uint32_t h2u(__half2 v) {
    return *reinterpret_cast<uint32_t*>(&v);
}
__device__ __forceinline__ uint2 hi_f4(float4 v) {
    uint2 h;
    h.x = h2u(__floats2half2_rn(v.x, v.y));
    h.y = h2u(__floats2half2_rn(v.z, v.w));
    return h;
}
// monotonic (distance, index) key: smaller distance, then smaller index
__device__ __forceinline__ ull packkey(float d, int idx) {
    uint32_t u = __float_as_uint(d);
    u ^= (u >> 31) ? 0xFFFFFFFFu : 0x80000000u;
    return ((ull)u << 32) | (uint32_t)idx;
}

// ---------------------------------------------------------------------------
__global__ void cnorm_kernel(const float* __restrict__ emb) {
    int warp = (blockIdx.x * blockDim.x + threadIdx.x) >> 5;
    int lane = threadIdx.x & 31;
    if (warp >= KCODE) return;
    const float* row = emb + (size_t)warp * DDIM;
    float s = 0.f;
    #pragma unroll
    for (int k = lane; k < DDIM; k += 32) { float v = row[k]; s += v * v; }
    #pragma unroll
    for (int o = 16; o; o >>= 1) s += __shfl_xor_sync(0xffffffffu, s, o);
    if (lane == 0) g_cnorm[warp] = s;
}

// ---------------------------------------------------------------------------
// 256 threads = 8 warps 4(m)x2(n), warp tile 32x64 (hh coarse) + fused rescue.
// CTA b: rows [(b>>2)*128, +128), codes [(b&3)*256, +256).
// ---------------------------------------------------------------------------
__global__ __launch_bounds__(256, 2)
void vq_coarse_kernel(const float* __restrict__ x,
                      const float* __restrict__ emb) {
    extern __shared__ __half hsm[];
    __shared__ float cn_s[SEGK];
    __shared__ float sV[2][BM];
    __shared__ int2  list[CAP];
    __shared__ int   cnt;
    __shared__ ull   keys[BM];

    const int tid = threadIdx.x;
    const int wid = tid >> 5;
    const int L   = tid & 31;
    const int rowBase = (blockIdx.x >> 2) * BM;
    const int segBase = (blockIdx.x & 3) * SEGK;
    const int mbase = (wid >> 1) * 32;
    const int nbase = (wid & 1) * 64;

    const uint32_t SB = smem_u32(hsm);
    const int aRow = (L & 7) + 8 * ((L >> 3) & 1);
    const int aK   = (L >> 4) * 16;
    const uint32_t aBase = (uint32_t)((mbase + aRow) * 80 + aK);
    const uint32_t bBase = (uint32_t)((nbase + aRow) * 80 + aK);

    const int lRow = tid >> 1;
    const int lKh  = (tid & 1) * 16;

    cn_s[tid] = g_cnorm[segBase + tid];
    if (tid == 0) cnt = 0;
    if (tid < BM) keys[tid] = ~0ull;

    float4 vS[4];

    #define LOAD_A(sidx) do { \
        const int _ko = ((sidx) & 7) * KS + lKh; \
        const float* xp = x + (size_t)(rowBase + lRow) * DDIM + _ko; \
        vS[0] = *(const float4*)(xp);      vS[1] = *(const float4*)(xp + 4); \
        vS[2] = *(const float4*)(xp + 8);  vS[3] = *(const float4*)(xp + 12); \
    } while (0)

    #define LOAD_B(sidx) do { \
        const int _t  = (sidx) >> 3; \
        const int _ko = ((sidx) & 7) * KS + lKh; \
        const float* bp = emb + (size_t)(segBase + _t * BN + lRow) * DDIM + _ko; \
        vS[0] = *(const float4*)(bp);      vS[1] = *(const float4*)(bp + 4); \
        vS[2] = *(const float4*)(bp + 8);  vS[3] = *(const float4*)(bp + 12); \
    } while (0)

    #define STORE_HI(matH) do { \
        const int _hb = lRow * PITCHH + lKh; \
        uint4 _p0, _p1; \
        uint2 _a = hi_f4(vS[0]), _b = hi_f4(vS[1]); \
        uint2 _c = hi_f4(vS[2]), _d = hi_f4(vS[3]); \
        _p0.x = _a.x; _p0.y = _a.y; _p0.z = _b.x; _p0.w = _b.y; \
        _p1.x = _c.x; _p1.y = _c.y; _p1.z = _d.x; _p1.w = _d.y; \
        *(uint4*)&hsm[(matH) + _hb]     = _p0; \
        *(uint4*)&hsm[(matH) + _hb + 8] = _p1; \
    } while (0)

    float acc[2][8][4];
    #pragma unroll
    for (int f = 0; f < 2; ++f)
        #pragma unroll
        for (int n = 0; n < 8; ++n)
            #pragma unroll
            for (int e = 0; e < 4; ++e) acc[f][n][e] = 0.f;

    LOAD_A(0); STORE_HI(0);
    LOAD_B(0); STORE_HI(2 * MAT_H);
    __syncthreads();

    for (int g = 0; g < NG; ++g) {
        const int buf = g & 1;
        const uint32_t AHB = SB + (uint32_t)(buf * MAT_H) * 2;
        const uint32_t BHB = SB + (uint32_t)((2 + buf) * MAT_H) * 2;
        const int ahN = (buf ^ 1) * MAT_H;
        const int bhN = (2 + (buf ^ 1)) * MAT_H;
        const bool pf = (g + 1 < NG);

        if (pf) LOAD_A(g + 1);

        #pragma unroll
        for (int kk = 0; kk < 2; ++kk) {
            const uint32_t kof = (uint32_t)(kk * 32);
            uint32_t ah[2][4], bh[4][4];
            #pragma unroll
            for (int f = 0; f < 2; ++f) LDSM4(ah[f], AHB + aBase + f * 1280 + kof);
            #pragma unroll
            for (int q = 0; q < 4; ++q) LDSM4(bh[q], BHB + bBase + q * 1280 + kof);
            #pragma unroll
            for (int f = 0; f < 2; ++f)
                #pragma unroll
                for (int q = 0; q < 4; ++q) {
                    mma_f16(acc[f][2 * q],     ah[f], bh[q][0], bh[q][2]);
                    mma_f16(acc[f][2 * q + 1], ah[f], bh[q][1], bh[q][3]);
                }
            if (kk == 0) { if (pf) { STORE_HI(ahN); LOAD_B(g + 1); } }
            else         { if (pf) STORE_HI(bhN); }
        }

        // ---- tile epilogue: fold -0.5*cn, per-row tile max, band candidates ----
        if ((g & 7) == 7) {
            const int tileB = (g >> 3) * BN;     // local code base 0/128
            // fold norm term (scores now exact-form coarse scores)
            #pragma unroll
            for (int n = 0; n < 8; ++n) {
                const int c0 = tileB + nbase + 8 * n + 2 * (L & 3);
                const float hc0 = -0.5f * cn_s[c0];
                const float hc1 = -0.5f * cn_s[c0 + 1];
                #pragma unroll
                for (int f = 0; f < 2; ++f) {
                    acc[f][n][0] += hc0; acc[f][n][1] += hc1;
                    acc[f][n][2] += hc0; acc[f][n][3] += hc1;
                }
            }
            // per-row max over this warp's 64 codes
            #pragma unroll
            for (int f = 0; f < 2; ++f)
                #pragma unroll
                for (int h = 0; h < 2; ++h) {
                    float m = -CUDART_INF_F;
                    #pragma unroll
                    for (int n = 0; n < 8; ++n) {
                        m = fmaxf(m, acc[f][n][2 * h]);
                        m = fmaxf(m, acc[f][n][2 * h + 1]);
                    }
                    m = fmaxf(m, __shfl_xor_sync(0xffffffffu, m, 1));
                    m = fmaxf(m, __shfl_xor_sync(0xffffffffu, m, 2));
                    if ((L & 3) == 0)
                        sV[wid & 1][mbase + 16 * f + 8 * h + (L >> 2)] = m;
                }
            __syncthreads();
            // threshold & candidate scan
            #pragma unroll
            for (int f = 0; f < 2; ++f)
                #pragma unroll
                for (int h = 0; h < 2; ++h) {
                    const int row = mbase + 16 * f + 8 * h + (L >> 2);
                    const float thr = fmaxf(sV[0][row], sV[1][row]) - BAND;
                    #pragma unroll
                    for (int n = 0; n < 8; ++n)
                        #pragma unroll
                        for (int e = 0; e < 2; ++e) {
                            if (acc[f][n][2 * h + e] >= thr) {
                                int pos = atomicAdd(&cnt, 1);
                                if (pos < CAP) {
                                    int code = segBase + tileB + nbase + 8 * n
                                             + 2 * (L & 3) + e;
                                    list[pos] = make_int2(row, code);
                                }
                            }
                        }
                }
            if (g + 1 < NG) {
                #pragma unroll
                for (int f = 0; f < 2; ++f)
                    #pragma unroll
                    for (int n = 0; n < 8; ++n)
                        #pragma unroll
                        for (int e = 0; e < 4; ++e) acc[f][n][e] = 0.f;
            }
        }
        __syncthreads();
    }

    // ---- rescue: exact fp32 rescoring of candidates ----
    const int total = min(cnt, CAP);
    for (int ei = wid; ei < total; ei += 8) {
        const int2 ent = list[ei];
        const float4* xr = (const float4*)(x + (size_t)(rowBase + ent.x) * DDIM + L * 8);
        const float4* cr = (const float4*)(emb + (size_t)ent.y * DDIM + L * 8);
        float4 a0 = xr[0], a1 = xr[1];
        float4 b0 = cr[0], b1 = cr[1];
        float p = a0.x * b0.x + a0.y * b0.y + a0.z * b0.z + a0.w * b0.w
                + a1.x * b1.x + a1.y * b1.y + a1.z * b1.z + a1.w * b1.w;
        #pragma unroll
        for (int o = 16; o; o >>= 1) p += __shfl_xor_sync(0xffffffffu, p, o);
        if (L == 0) {
            float d = fmaf(-2.f, p, cn_s[ent.y - segBase]);
            atomicMin(&keys[ent.x], packkey(d, ent.y));
        }
    }
    __syncthreads();
    if (tid < BM)
        g_candKey[(size_t)(blockIdx.x & 3) * NTOK + rowBase + tid] = keys[tid];
}

// ---------------------------------------------------------------------------
// Merge 4 segment keys per row, write indices, gather outputs.
// 128 blocks x 256 threads; block covers 256 rows.
// ---------------------------------------------------------------------------
__global__ __launch_bounds__(256)
void merge_kernel(const float* __restrict__ emb, float* __restrict__ out) {
    __shared__ int bidx_s[256];
    const int tid = threadIdx.x;
    const int row = blockIdx.x * 256 + tid;

    ull k = g_candKey[row];
    #pragma unroll
    for (int s = 1; s < NSEG; ++s) {
        ull ks = g_candKey[(size_t)s * NTOK + row];
        if (ks < k) k = ks;
    }
    const int idx = (int)(k & 0xFFFFFFFFull);
    bidx_s[tid] = idx;
    out[OUT_IDX + row] = (float)idx;
    __syncthreads();

    const float4* emb4 = (const float4*)emb;
    float4* o4 = (float4*)out;
    const int rowBase = blockIdx.x * 256;
    #pragma unroll 4
    for (int it = 0; it < 64; ++it) {
        int gg = tid + it * 256;
        int m = gg >> 6;
        int q = gg & 63;
        int code = bidx_s[m];
        float4 val = emb4[(size_t)code * 64 + q];
        size_t off = (size_t)(rowBase + m) * 64 + q;
        o4[off] = val;
        o4[off + (OUT_BAR / 4)] = val;
    }
}

// ---------------------------------------------------------------------------
extern "C" void kernel_launch(void* const* d_in, const int* in_sizes, int n_in,
                              void* d_out, int out_size) {
    const float* x   = (const float*)d_in[0];
    const float* emb = (const float*)d_in[1];
    float* out = (float*)d_out;

    cudaFuncSetAttribute(vq_coarse_kernel, cudaFuncAttributeMaxDynamicSharedMemorySize, DYN_SMEM);

    cnorm_kernel<<<KCODE / 8, 256>>>(emb);
    vq_coarse_kernel<<<(NTOK / BM) * NSEG, 256, DYN_SMEM>>>(x, emb);
    merge_kernel<<<NTOK / 256, 256>>>(emb, out);
}